// round 2
// baseline (speedup 1.0000x reference)
#include <cuda_runtime.h>

typedef unsigned long long ull;

// ---- f32x2 packed helpers (Blackwell sm_103a) ----
__device__ __forceinline__ ull pk(float lo, float hi) {
    ull r;
    asm("mov.b64 %0, {%1,%2};" : "=l"(r)
        : "r"(__float_as_uint(lo)), "r"(__float_as_uint(hi)));
    return r;
}
__device__ __forceinline__ void upk(ull v, float& lo, float& hi) {
    unsigned a, b;
    asm("mov.b64 {%0,%1}, %2;" : "=r"(a), "=r"(b) : "l"(v));
    lo = __uint_as_float(a);
    hi = __uint_as_float(b);
}
__device__ __forceinline__ ull fma2(ull a, ull b, ull c) {
    ull d;
    asm("fma.rn.f32x2 %0, %1, %2, %3;" : "=l"(d) : "l"(a), "l"(b), "l"(c));
    return d;
}

#define H    128   // hidden dim
#define TPB  64    // threads per block
#define PPT  8     // points per thread
#define NPR  4     // point-pairs per thread

__global__ __launch_bounds__(TPB)
void cubeflow_fused_kernel(const float* __restrict__ input,
                           const float* __restrict__ latent,
                           const float* __restrict__ W1,
                           const float* __restrict__ b1,
                           const float* __restrict__ W2,
                           const float* __restrict__ b2,
                           float* __restrict__ out,
                           int P, int BP)
{
    // Weights pre-duplicated as (w,w) f32x2 pairs; theta-bias folded in.
    // Inner loop: 3x LDS.128 -> pure fma2, zero pack MOVs, no bias fma.
    __shared__ float4 sWa[H];  // (w0,w0, w1,w1)
    __shared__ float4 sWb[H];  // (w2,w2, biasT,biasT)  biasT = w3*theta + b1
    __shared__ float4 sWc[H];  // (w20,w20, w21,w21)

    const int tid  = threadIdx.x;
    const int unit = blockIdx.x * TPB + tid;       // one unit = 8 points
    const int p0   = unit * PPT;

    // theta is uniform per block (block spans 512 contiguous points, P % 512 == 0)
    const int   bidx  = (blockIdx.x * (TPB * PPT)) / P;
    const float theta = latent[bidx] * 10.0f;

    #pragma unroll
    for (int h = tid; h < H; h += TPB) {
        const float4 r  = reinterpret_cast<const float4*>(W1)[h];
        const float  bb = fmaf(r.w, theta, b1[h]);
        const float  w20 = W2[h], w21 = W2[H + h];
        sWa[h] = make_float4(r.x, r.x, r.y, r.y);
        sWb[h] = make_float4(r.z, r.z, bb, bb);
        sWc[h] = make_float4(w20, w20, w21, w21);
    }
    __syncthreads();

    float sn, cs;
    sincosf(theta, &sn, &cs);

    // 8 points * 3 coords = 24 floats = 6 coalesced float4 loads
    const float4* in4 = reinterpret_cast<const float4*>(input) + (size_t)unit * 6;
    float4 q[6];
    #pragma unroll
    for (int i = 0; i < 6; ++i) q[i] = in4[i];
    const float* qf = reinterpret_cast<const float*>(q);

    float x0[PPT], x1[PPT], x2[PPT];
    #pragma unroll
    for (int k = 0; k < PPT; ++k) {
        x0[k] = qf[3 * k + 0];
        x1[k] = qf[3 * k + 1];
        x2[k] = qf[3 * k + 2];
    }

    // ---- cubeflow (z-rotation closed form) + eval/con stores ----
    float ev[PPT];
    #pragma unroll
    for (int k = 0; k < PPT; ++k) {
        const float d0 = x0[k] - theta, d1 = x1[k], d2 = x2[k];
        const float f1 = 1.4f * (d0 * d0) + 1.4f * (d1 * d1)
                       + 0.2f * (d2 * d2) - 0.5f;
        const float a2  = d2 + 0.4f;
        const float c20 = d0 * cs + d1 * sn;
        const float c21 = d1 * cs - d0 * sn;
        const float f2v = 3.8f * c20 * c20 + 0.6f * c21 * c21
                        + 3.8f * a2 * a2 - 0.5f;
        const float a3  = d2 - 0.6f;
        const float c30 = d0 * cs - d1 * sn;
        const float c31 = d0 * sn + d1 * cs;
        const float f3v = 0.35f * c30 * c30 + 2.8f * c31 * c31
                        + 2.8f * a3 * a3 - 0.5f;
        ev[k] = fminf(f1, fminf(f2v, f3v));
    }
    float4* evp = reinterpret_cast<float4*>(out + p0);
    evp[0] = make_float4(ev[0], ev[1], ev[2], ev[3]);
    evp[1] = make_float4(ev[4], ev[5], ev[6], ev[7]);

    float4* conp = reinterpret_cast<float4*>(out + BP) + p0;   // con: float4/point
    #pragma unroll
    for (int k = 0; k < PPT; ++k)
        conp[k] = make_float4(x0[k], x1[k], x2[k], theta);

    // ---- MLP: two adjacent POINTS per f32x2 lane ----
    ull X0[NPR], X1[NPR], X2[NPR], A0[NPR], A1[NPR];
    #pragma unroll
    for (int j = 0; j < NPR; ++j) {
        X0[j] = pk(x0[2 * j], x0[2 * j + 1]);
        X1[j] = pk(x1[2 * j], x1[2 * j + 1]);
        X2[j] = pk(x2[2 * j], x2[2 * j + 1]);
        A0[j] = 0ull;
        A1[j] = 0ull;
    }

    const ulonglong2* pa = reinterpret_cast<const ulonglong2*>(sWa);
    const ulonglong2* pb = reinterpret_cast<const ulonglong2*>(sWb);
    const ulonglong2* pc = reinterpret_cast<const ulonglong2*>(sWc);

    #pragma unroll 4
    for (int h = 0; h < H; ++h) {
        const ulonglong2 va = pa[h];   // va.x = (w0,w0), va.y = (w1,w1)
        const ulonglong2 vb = pb[h];   // vb.x = (w2,w2), vb.y = (biasT,biasT)
        const ulonglong2 vc = pc[h];   // vc.x = (w20,w20), vc.y = (w21,w21)
        #pragma unroll
        for (int j = 0; j < NPR; ++j) {
            ull t = fma2(va.x, X0[j],
                    fma2(va.y, X1[j],
                    fma2(vb.x, X2[j], vb.y)));
            float lo, hi;
            upk(t, lo, hi);
            lo = fmaxf(lo, 0.0f);            // relu on ALU pipe
            hi = fmaxf(hi, 0.0f);
            t = pk(lo, hi);
            A0[j] = fma2(vc.x, t, A0[j]);    // lanes = (pt 2j, pt 2j+1)
            A1[j] = fma2(vc.y, t, A1[j]);
        }
    }

    const float b20 = __ldg(b2), b21 = __ldg(b2 + 1);
    float4* prp = reinterpret_cast<float4*>(out + (size_t)5 * BP + (size_t)p0 * 2);
    #pragma unroll
    for (int j = 0; j < NPR; ++j) {
        float a0l, a0h, a1l, a1h;
        upk(A0[j], a0l, a0h);
        upk(A1[j], a1l, a1h);
        prp[j] = make_float4(a0l + b20, a1l + b21, a0h + b20, a1h + b21);
    }
}

extern "C" void kernel_launch(void* const* d_in, const int* in_sizes, int n_in,
                              void* d_out, int out_size)
{
    const float* input  = (const float*)d_in[0];
    const float* latent = (const float*)d_in[1];
    const float* W1     = (const float*)d_in[2];
    const float* b1     = (const float*)d_in[3];
    const float* W2     = (const float*)d_in[4];
    const float* b2     = (const float*)d_in[5];
    float*       out    = (float*)d_out;

    const int BP = in_sizes[0] / 3;        // total points (B*P)
    const int B  = in_sizes[1];            // latent element count == batch
    const int P  = BP / B;
    const int units  = BP / PPT;
    const int blocks = units / TPB;

    cubeflow_fused_kernel<<<blocks, TPB>>>(input, latent, W1, b1, W2, b2,
                                           out, P, BP);
}

// round 3
// speedup vs baseline: 1.2892x; 1.2892x over previous
#include <cuda_runtime.h>

typedef unsigned long long ull;

// ---- f32x2 packed helpers (Blackwell sm_103a) ----
__device__ __forceinline__ ull pk(float lo, float hi) {
    ull r;
    asm("mov.b64 %0, {%1,%2};" : "=l"(r)
        : "r"(__float_as_uint(lo)), "r"(__float_as_uint(hi)));
    return r;
}
__device__ __forceinline__ void upk(ull v, float& lo, float& hi) {
    unsigned a, b;
    asm("mov.b64 {%0,%1}, %2;" : "=r"(a), "=r"(b) : "l"(v));
    lo = __uint_as_float(a);
    hi = __uint_as_float(b);
}
__device__ __forceinline__ ull fma2(ull a, ull b, ull c) {
    ull d;
    asm("fma.rn.f32x2 %0, %1, %2, %3;" : "=l"(d) : "l"(a), "l"(b), "l"(c));
    return d;
}

#define H    128   // hidden dim
#define HP   64    // h-pairs total
#define HPH  32    // h-pairs per half
#define TPB  256   // threads per block (two 128-thread halves)
#define UPB  128   // point-units per block
#define PPT  4     // points per unit

__global__ __launch_bounds__(TPB, 4)
void cubeflow_fused_kernel(const float* __restrict__ input,
                           const float* __restrict__ latent,
                           const float* __restrict__ W1,
                           const float* __restrict__ b1,
                           const float* __restrict__ W2,
                           const float* __restrict__ b2,
                           float* __restrict__ out,
                           int P, int BP)
{
    // Even/odd-h packed weights (no duplication): 48B per h-pair.
    __shared__ float4 sA[HP];   // (w0e,w0o, w1e,w1o)
    __shared__ float4 sB[HP];   // (w2e,w2o, bTe,bTo)   bT = w3*theta + b1
    __shared__ float4 sC[HP];   // (w20e,w20o, w21e,w21o)
    __shared__ float4 redA[UPB];  // cross-half partial probs (pts 0,1)
    __shared__ float4 redB[UPB];  // cross-half partial probs (pts 2,3)

    const int tid    = threadIdx.x;
    const int wg_tid = tid & (UPB - 1);
    const int half   = tid >> 7;                     // 0: h[0,64)  1: h[64,128)

    // theta uniform per block: block spans 512 contiguous points within a batch
    const int   bidx  = (blockIdx.x * (UPB * PPT)) / P;
    const float theta = latent[bidx] * 10.0f;

    if (tid < HP) {
        const int h0 = 2 * tid, h1 = h0 + 1;
        const float4 r0 = reinterpret_cast<const float4*>(W1)[h0];
        const float4 r1 = reinterpret_cast<const float4*>(W1)[h1];
        sA[tid] = make_float4(r0.x, r1.x, r0.y, r1.y);
        sB[tid] = make_float4(r0.z, r1.z,
                              fmaf(r0.w, theta, b1[h0]),
                              fmaf(r1.w, theta, b1[h1]));
        sC[tid] = make_float4(W2[h0], W2[h1], W2[H + h0], W2[H + h1]);
    }
    __syncthreads();

    const int unit = blockIdx.x * UPB + wg_tid;      // one unit = 4 points
    const int p0   = unit * PPT;

    // 4 points * 3 coords = 3 coalesced float4 loads (both halves load)
    const float4* in4 = reinterpret_cast<const float4*>(input) + (size_t)unit * 3;
    const float4 q0 = in4[0], q1 = in4[1], q2 = in4[2];
    const float x0[PPT] = { q0.x, q0.w, q1.z, q2.y };
    const float x1[PPT] = { q0.y, q1.x, q1.w, q2.z };
    const float x2[PPT] = { q0.z, q1.y, q2.x, q2.w };

    // lower half: con stores (overlaps with MLP latency)
    if (half == 0) {
        float4* conp = reinterpret_cast<float4*>(out + BP) + p0;
        #pragma unroll
        for (int k = 0; k < PPT; ++k)
            conp[k] = make_float4(x0[k], x1[k], x2[k], theta);
    }

    // ---- MLP over this half's 32 h-pairs; x duplicated into both lanes ----
    ull X0[PPT], X1[PPT], X2[PPT], A0[PPT], A1[PPT];
    #pragma unroll
    for (int k = 0; k < PPT; ++k) {
        X0[k] = pk(x0[k], x0[k]);
        X1[k] = pk(x1[k], x1[k]);
        X2[k] = pk(x2[k], x2[k]);
        A0[k] = 0ull;
        A1[k] = 0ull;
    }

    const ulonglong2* pa = reinterpret_cast<const ulonglong2*>(sA) + half * HPH;
    const ulonglong2* pb = reinterpret_cast<const ulonglong2*>(sB) + half * HPH;
    const ulonglong2* pc = reinterpret_cast<const ulonglong2*>(sC) + half * HPH;

    #pragma unroll 4
    for (int hp = 0; hp < HPH; ++hp) {
        const ulonglong2 va = pa[hp];   // (w0 pair, w1 pair)
        const ulonglong2 vb = pb[hp];   // (w2 pair, biasT pair)
        const ulonglong2 vc = pc[hp];   // (w20 pair, w21 pair)
        #pragma unroll
        for (int k = 0; k < PPT; ++k) {
            ull t = fma2(va.x, X0[k],
                    fma2(va.y, X1[k],
                    fma2(vb.x, X2[k], vb.y)));
            float lo, hi;
            upk(t, lo, hi);
            lo = fmaxf(lo, 0.0f);
            hi = fmaxf(hi, 0.0f);
            t = pk(lo, hi);
            A0[k] = fma2(vc.x, t, A0[k]);
            A1[k] = fma2(vc.y, t, A1[k]);
        }
    }

    // horizontal fold (even-h + odd-h lanes)
    float pr0[PPT], pr1[PPT];
    #pragma unroll
    for (int k = 0; k < PPT; ++k) {
        float l, h;
        upk(A0[k], l, h); pr0[k] = l + h;
        upk(A1[k], l, h); pr1[k] = l + h;
    }

    if (half == 1) {
        // upper half: eval (z-rotation closed form) + publish partial probs
        float sn, cs;
        sincosf(theta, &sn, &cs);
        float ev[PPT];
        #pragma unroll
        for (int k = 0; k < PPT; ++k) {
            const float d0 = x0[k] - theta, d1 = x1[k], d2 = x2[k];
            const float f1 = 1.4f * (d0 * d0) + 1.4f * (d1 * d1)
                           + 0.2f * (d2 * d2) - 0.5f;
            const float a2  = d2 + 0.4f;
            const float c20 = d0 * cs + d1 * sn;
            const float c21 = d1 * cs - d0 * sn;
            const float f2v = 3.8f * c20 * c20 + 0.6f * c21 * c21
                            + 3.8f * a2 * a2 - 0.5f;
            const float a3  = d2 - 0.6f;
            const float c30 = d0 * cs - d1 * sn;
            const float c31 = d0 * sn + d1 * cs;
            const float f3v = 0.35f * c30 * c30 + 2.8f * c31 * c31
                            + 2.8f * a3 * a3 - 0.5f;
            ev[k] = fminf(f1, fminf(f2v, f3v));
        }
        *reinterpret_cast<float4*>(out + p0) =
            make_float4(ev[0], ev[1], ev[2], ev[3]);

        redA[wg_tid] = make_float4(pr0[0], pr1[0], pr0[1], pr1[1]);
        redB[wg_tid] = make_float4(pr0[2], pr1[2], pr0[3], pr1[3]);
    }
    __syncthreads();

    if (half == 0) {
        const float b20 = __ldg(b2), b21 = __ldg(b2 + 1);
        const float4 rA = redA[wg_tid];
        const float4 rB = redB[wg_tid];
        float4* prp = reinterpret_cast<float4*>(out + (size_t)5 * BP
                                                + (size_t)p0 * 2);
        prp[0] = make_float4(pr0[0] + rA.x + b20, pr1[0] + rA.y + b21,
                             pr0[1] + rA.z + b20, pr1[1] + rA.w + b21);
        prp[1] = make_float4(pr0[2] + rB.x + b20, pr1[2] + rB.y + b21,
                             pr0[3] + rB.z + b20, pr1[3] + rB.w + b21);
    }
}

extern "C" void kernel_launch(void* const* d_in, const int* in_sizes, int n_in,
                              void* d_out, int out_size)
{
    const float* input  = (const float*)d_in[0];
    const float* latent = (const float*)d_in[1];
    const float* W1     = (const float*)d_in[2];
    const float* b1     = (const float*)d_in[3];
    const float* W2     = (const float*)d_in[4];
    const float* b2     = (const float*)d_in[5];
    float*       out    = (float*)d_out;

    const int BP = in_sizes[0] / 3;        // total points (B*P)
    const int B  = in_sizes[1];            // latent element count == batch
    const int P  = BP / B;
    const int blocks = BP / (UPB * PPT);   // 1024

    cubeflow_fused_kernel<<<blocks, TPB>>>(input, latent, W1, b1, W2, b2,
                                           out, P, BP);
}